// round 13
// baseline (speedup 1.0000x reference)
#include <cuda_runtime.h>

#define F 16384
#define NJ 22
#define STRIDE (NJ*3)   // 66 floats per frame
#define NBINS 25
#define NUNITS 80       // total (bin, i-row) work units
#define INV4PI 0.07957747154594767f
#define PIO2 1.5707963267948966f
#define TF 16           // frames per transpose tile (1024 blocks -> ~7/SM)

// ---------------- device scratch (no allocs allowed) ----------------
__device__ float g_m1T[STRIDE * F];   // [j*3+c][frame]
__device__ float g_m2T[STRIDE * F];
__device__ unsigned char g_flag[F];
__device__ float g_part[NUNITS * F];  // per-(bin,row) partial sums, [u][frame]

__constant__ int c_pathj[5][5] = {
    {2, 5, 8, 11, 0},
    {1, 4, 7, 10, 0},
    {3, 6, 9, 12, 15},
    {14, 17, 19, 21, 0},
    {13, 16, 18, 20, 0}
};
__constant__ int c_plen[5] = {4, 4, 5, 4, 4};

// unit -> bin / row tables. rows per a-path: {3,3,4,3,3}; bin = a*5+b.
__constant__ unsigned char c_ubin[NUNITS] = {
    0,0,0, 1,1,1, 2,2,2, 3,3,3, 4,4,4,
    5,5,5, 6,6,6, 7,7,7, 8,8,8, 9,9,9,
    10,10,10,10, 11,11,11,11, 12,12,12,12, 13,13,13,13, 14,14,14,14,
    15,15,15, 16,16,16, 17,17,17, 18,18,18, 19,19,19,
    20,20,20, 21,21,21, 22,22,22, 23,23,23, 24,24,24
};
__constant__ unsigned char c_urow[NUNITS] = {
    0,1,2, 0,1,2, 0,1,2, 0,1,2, 0,1,2,
    0,1,2, 0,1,2, 0,1,2, 0,1,2, 0,1,2,
    0,1,2,3, 0,1,2,3, 0,1,2,3, 0,1,2,3, 0,1,2,3,
    0,1,2, 0,1,2, 0,1,2, 0,1,2, 0,1,2,
    0,1,2, 0,1,2, 0,1,2, 0,1,2, 0,1,2
};
__constant__ int c_ustart[NBINS + 1] = {
    0,3,6,9,12,15,18,21,24,27,30,34,38,42,46,50,53,56,59,62,65,68,71,74,77,80
};

// ---------------- small vec helpers ----------------
struct V3 { float x, y, z; };

__device__ __forceinline__ V3 vsub(V3 a, V3 b) { return {a.x - b.x, a.y - b.y, a.z - b.z}; }
__device__ __forceinline__ V3 vcrs(V3 a, V3 b) {
    return {fmaf(a.y, b.z, -a.z * b.y),
            fmaf(a.z, b.x, -a.x * b.z),
            fmaf(a.x, b.y, -a.y * b.x)};
}
__device__ __forceinline__ float vdot(V3 a, V3 b) {
    return fmaf(a.x, b.x, fmaf(a.y, b.y, a.z * b.z));
}
// _safe_normalize semantics: zero vector -> zero scale (downstream dot -> 0)
__device__ __forceinline__ float invnorm(V3 v) {
    float n2 = vdot(v, v);
    return (n2 > 0.f) ? rsqrtf(n2) : 0.f;
}

// Branch-free asin (A&S 4.4.45). For |d| >= 1 the s>0 guard yields exactly
// +-pi/2, identical to clipping first.
__device__ __forceinline__ float fast_asin(float d) {
    float ax = fabsf(d);
    float p = fmaf(ax, -0.0012624911f, 0.0066700901f);
    p = fmaf(ax, p, -0.0170881256f);
    p = fmaf(ax, p,  0.0308918810f);
    p = fmaf(ax, p, -0.0501743046f);
    p = fmaf(ax, p,  0.0889789874f);
    p = fmaf(ax, p, -0.2145988016f);
    p = fmaf(ax, p,  1.5707963050f);
    float s = 1.0f - ax;
    float r = (s > 0.f) ? (s * rsqrtf(s)) * p : 0.f;   // sqrt(s)*p via MUFU.RSQ
    return copysignf(PIO2 - r, d);
}

// ---------------- kernel 1: transpose (both motions) + window flag --------
// float4-vectorized on both global sides; smem scalar (padded, conflict-free)
__global__ void __launch_bounds__(256) transpose_mask_kernel(
        const float* __restrict__ m1, const float* __restrict__ m2) {
    __shared__ float t1[TF * 67];   // padded stride 67 -> conflict-free
    __shared__ float t2[TF * 67];
    int f0 = blockIdx.x * TF;

    // read: TF*STRIDE = 1056 floats = 264 float4 (block base is 16B-aligned)
    const float4* in1 = (const float4*)(m1 + f0 * STRIDE);
    const float4* in2 = (const float4*)(m2 + f0 * STRIDE);
    for (int q = threadIdx.x; q < TF * STRIDE / 4; q += 256) {
        float4 v1 = in1[q];
        float4 v2 = in2[q];
        int base = q * 4;
        int fl = base / STRIDE, sl = base % STRIDE;  // sl..sl+3 < 66? STRIDE=66, 4 | base but 66 not mult of 4 -> may cross
        // handle potential frame-boundary crossing element-wise
        float vs1[4] = {v1.x, v1.y, v1.z, v1.w};
        float vs2[4] = {v2.x, v2.y, v2.z, v2.w};
#pragma unroll
        for (int e = 0; e < 4; e++) {
            int s = sl + e, ff = fl;
            if (s >= STRIDE) { s -= STRIDE; ff++; }
            t1[ff * 67 + s] = vs1[e];
            t2[ff * 67 + s] = vs2[e];
        }
    }
    __syncthreads();
    // write: per (slot, fl4) a float4 of 4 consecutive frames
    for (int q = threadIdx.x; q < STRIDE * TF / 4; q += 256) {
        int slot = q >> 2;          // q / 4
        int fl4 = q & 3;            // 4 frames per float4
        int fl = fl4 * 4;
        float4 w1 = make_float4(t1[(fl + 0) * 67 + slot], t1[(fl + 1) * 67 + slot],
                                t1[(fl + 2) * 67 + slot], t1[(fl + 3) * 67 + slot]);
        float4 w2 = make_float4(t2[(fl + 0) * 67 + slot], t2[(fl + 1) * 67 + slot],
                                t2[(fl + 2) * 67 + slot], t2[(fl + 3) * 67 + slot]);
        *(float4*)(g_m1T + slot * F + f0 + fl) = w1;
        *(float4*)(g_m2T + slot * F + f0 + fl) = w2;
    }
    // XZ bbox overlap flags for this block's TF frames (from smem)
    if (threadIdx.x < TF) {
        int fl = threadIdx.x;
        float x1n = 1e30f, x1x = -1e30f, z1n = 1e30f, z1x = -1e30f;
        float x2n = 1e30f, x2x = -1e30f, z2n = 1e30f, z2x = -1e30f;
#pragma unroll
        for (int j = 0; j < NJ; j++) {
            float x1 = t1[fl * 67 + j * 3 + 0];
            float z1 = t1[fl * 67 + j * 3 + 2];
            float x2 = t2[fl * 67 + j * 3 + 0];
            float z2 = t2[fl * 67 + j * 3 + 2];
            x1n = fminf(x1n, x1); x1x = fmaxf(x1x, x1);
            z1n = fminf(z1n, z1); z1x = fmaxf(z1x, z1);
            x2n = fminf(x2n, x2); x2x = fmaxf(x2x, x2);
            z2n = fminf(z2n, z2); z2x = fmaxf(z2x, z2);
        }
        bool ovx = !((x1x < x2n) || (x2x < x1n));
        bool ovz = !((z1x < z2n) || (z2x < z1n));
        g_flag[f0 + fl] = (unsigned char)(ovx && ovz);
    }
}

// ---------------- one i-row of the GLI pair sum (j-reuse inside) -----------
// Across j -> j+1:  f3' = cross(r23',r13') = cross(r24,r14) = -f1.
// asin is odd -> the two f3' terms flip sign. Exact algebra.
template <int NB>
__device__ __forceinline__ float gli_row(int f, int a, int b, int i) {
    V3 P2[NB];
#pragma unroll
    for (int k = 0; k < NB; k++) {
        int j = c_pathj[b][k];
        P2[k].x = g_m2T[(j * 3 + 0) * F + f];
        P2[k].y = g_m2T[(j * 3 + 1) * F + f];
        P2[k].z = g_m2T[(j * 3 + 2) * F + f];
    }
    V3 s1, e1;
    {
        int j0 = c_pathj[a][i];
        int j1 = c_pathj[a][i + 1];
        s1.x = g_m1T[(j0 * 3 + 0) * F + f];
        s1.y = g_m1T[(j0 * 3 + 1) * F + f];
        s1.z = g_m1T[(j0 * 3 + 2) * F + f];
        e1.x = g_m1T[(j1 * 3 + 0) * F + f];
        e1.y = g_m1T[(j1 * 3 + 1) * F + f];
        e1.z = g_m1T[(j1 * 3 + 2) * F + f];
    }
    V3 r12 = vsub(e1, s1);

    float acc = 0.f;
    // ---- j = 0: full evaluation ----
    V3 r13 = vsub(P2[0], s1);
    V3 r14 = vsub(P2[1], s1);
    V3 r23 = vsub(r13, r12);
    V3 r24 = vsub(r14, r12);
    V3 f0v = vcrs(r13, r14);
    V3 f1v = vcrs(r14, r24);
    V3 f2v = vcrs(r24, r23);
    V3 f3v = vcrs(r23, r13);
    float r0 = invnorm(f0v), r1 = invnorm(f1v);
    float r2 = invnorm(f2v), r3 = invnorm(f3v);
    {
        float t = fast_asin(vdot(f0v, f1v) * (r0 * r1))
                + fast_asin(vdot(f1v, f2v) * (r1 * r2))
                + fast_asin(vdot(f2v, f3v) * (r2 * r3))
                + fast_asin(vdot(f3v, f0v) * (r3 * r0));
        V3 r34 = vsub(r14, r13);
        float sg = vdot(vcrs(r34, r12), r13);
        acc += (sg > 0.f) ? t : -t;
    }

    // carried state: f1v/r1 (previous f1), r14/r24 (become r13'/r23')
#pragma unroll
    for (int j = 1; j < NB - 1; j++) {
        V3 p13 = r14;              // r13' = previous r14
        V3 p23 = r24;              // r23' = previous r24
        r14 = vsub(P2[j + 1], s1);
        r24 = vsub(r14, r12);
        V3 nf0 = vcrs(p13, r14);
        V3 nf1 = vcrs(r14, r24);
        V3 nf2 = vcrs(r24, p23);
        float n0 = invnorm(nf0), n1 = invnorm(nf1), n2 = invnorm(nf2);
        // f3' = -f1(prev) with norm r1 -> last two asin terms negate
        float t = fast_asin(vdot(nf0, nf1) * (n0 * n1))
                + fast_asin(vdot(nf1, nf2) * (n1 * n2))
                - fast_asin(vdot(nf2, f1v) * (n2 * r1))
                - fast_asin(vdot(f1v, nf0) * (r1 * n0));
        V3 r34 = vsub(r14, p13);
        float sg = vdot(vcrs(r34, r12), p13);
        acc += (sg > 0.f) ? t : -t;
        f1v = nf1; r1 = n1;
    }
    return acc;
}

// ---------------- kernel 2: flat (frame x unit) GLI partials ---------------
// unit u = blockIdx.y*4 + threadIdx.y in [0,80): zero idle threads, no sync.
__global__ void __launch_bounds__(256) gli_kernel() {
    int f = blockIdx.x * 64 + threadIdx.x;
    int u = blockIdx.y * 4 + threadIdx.y;
    int bin = c_ubin[u];
    int a = bin / 5, b = bin % 5;
    int i = c_urow[u];
    int nb = c_plen[b];

    float part;
    if (nb == 5) part = gli_row<5>(f, a, b, i);   // warp-uniform branch
    else         part = gli_row<4>(f, a, b, i);

    g_part[u * F + f] = part;                     // coalesced store
}

// ---------------- kernel 3: sum partials, mask, max |delta| ----------------
// gli[bin][t] = (sum of its units) * mask[t] * INV4PI; out = max over bins
// of |gli[bin][t+1] - gli[bin][t]|.  block = (64 t, 4 bin-groups).
__global__ void vel_kernel(float* __restrict__ out) {
    __shared__ float red[4][64];
    int t = blockIdx.x * 64 + threadIdx.x;
    int g = threadIdx.y;
    int b0 = (g == 0) ? 0 : 7 + (g - 1) * 6;
    int b1 = (g == 0) ? 7 : b0 + 6;
    float best = 0.f;
    if (t < F - 1) {
        // window mask values at t and t+1
        bool mt = g_flag[t];
        if (t > 0) mt = mt || g_flag[t - 1];
        mt = mt || g_flag[t + 1];                  // t+1 <= F-1 valid
        bool mt1 = g_flag[t + 1] || g_flag[t];
        if (t + 2 < F) mt1 = mt1 || g_flag[t + 2];
        float m0 = mt ? 1.f : 0.f, m1 = mt1 ? 1.f : 0.f;

        for (int bin = b0; bin < b1; bin++) {
            float s0 = 0.f, s1 = 0.f;
            for (int u = c_ustart[bin]; u < c_ustart[bin + 1]; u++) {
                s0 += g_part[u * F + t];
                s1 += g_part[u * F + t + 1];
            }
            best = fmaxf(best, fabsf(m1 * s1 - m0 * s0));
        }
    }
    red[g][threadIdx.x] = best;
    __syncthreads();
    if (g == 0 && t < F - 1) {
        best = fmaxf(fmaxf(red[0][threadIdx.x], red[1][threadIdx.x]),
                     fmaxf(red[2][threadIdx.x], red[3][threadIdx.x]));
        out[t] = best * INV4PI;
    }
}

// ---------------- launcher ----------------
extern "C" void kernel_launch(void* const* d_in, const int* in_sizes, int n_in,
                              void* d_out, int out_size) {
    const float* m1 = (const float*)d_in[0];
    const float* m2 = (const float*)d_in[1];
    float* out = (float*)d_out;

    transpose_mask_kernel<<<F / TF, 256>>>(m1, m2);
    gli_kernel<<<dim3(F / 64, NUNITS / 4), dim3(64, 4)>>>();
    vel_kernel<<<F / 64, dim3(64, 4)>>>(out);
}